// round 16
// baseline (speedup 1.0000x reference)
#include <cuda_runtime.h>
#include <cuda_fp16.h>
#include <math.h>

#define NN 50000
#define HH 128
#define EE 800000
#define ECC 200000
#define STRIDE 64           // max in-degree bucket (Poisson(16): P(>64) ~ 1e-20)

// ---------------- scratch (no allocations allowed) ----------------
__device__ __half g_tmp[NN * HH];      // GEMM output messages (fp16)
__device__ __half g_hc[NN * HH];       // fp16 copy of final h for classifier
__device__ float  g_h[NN * HH];        // hidden after layer 1 (fp32)
__device__ float  g_dego[NN];          // deg_out^{-1/2}
__device__ float  g_degi[NN];          // deg_in^{-1/2}
__device__ int    g_cnt_out[NN];       // int out-degree
__device__ int    g_fill[NN];          // ELL fill cursor == in-degree
__device__ int    g_ell[NN * STRIDE];  // per-dst src lists, fixed stride

// ---------------- degree / ELL kernels ----------------
__global__ void zero_cnt_kernel() {
    int i = blockIdx.x * blockDim.x + threadIdx.x;
    if (i < NN) { g_cnt_out[i] = 0; g_fill[i] = 0; }
}

__global__ void build_graph_kernel(const int* __restrict__ src, const int* __restrict__ dst) {
    int i = blockIdx.x * blockDim.x + threadIdx.x;
    if (i < EE) {
        int s = src[i], d = dst[i];
        atomicAdd(&g_cnt_out[s], 1);
        int p = atomicAdd(&g_fill[d], 1);
        if (p < STRIDE) g_ell[d * STRIDE + p] = s;
    }
}

__global__ void make_scale_kernel() {
    int i = blockIdx.x * blockDim.x + threadIdx.x;
    if (i < NN) {
        int co = g_cnt_out[i]; if (co < 1) co = 1;
        int ci = g_fill[i];    if (ci < 1) ci = 1;
        g_dego[i] = rsqrtf((float)co);
        g_degi[i] = rsqrtf((float)ci);
    }
}

// ---------------- GEMM: g_tmp = fp16( (A @ W) [* dego[row]] ) ----------------
// 512 threads, tile 128x128, K in two 64-chunks (67.6 KB smem -> 2 CTAs/SM).
__global__ __launch_bounds__(512, 2) void gemm128_kernel(
    const float* __restrict__ A_ext, int use_gh,
    const float* __restrict__ W, int n, int apply_scale)
{
    extern __shared__ float sm[];
    float* sW = sm;                 // 64*128 floats (chunk)
    float* sA = sm + 64 * 128;      // 128*68 floats (chunk, 64 cols + 4 pad)

    const float* A = use_gh ? g_h : A_ext;
    int t = threadIdx.x;
    int row0 = blockIdx.x * 128;

    int rg = t >> 4;        // 0..31 : rows 4*rg .. 4*rg+3
    int cg = t & 15;        // float4 col-groups cg, cg+16
    const float4* sW4 = (const float4*)sW;

    float4 acc[4][2];
    #pragma unroll
    for (int r = 0; r < 4; ++r) {
        acc[r][0] = make_float4(0.f, 0.f, 0.f, 0.f);
        acc[r][1] = make_float4(0.f, 0.f, 0.f, 0.f);
    }

    #pragma unroll 1
    for (int c = 0; c < 2; ++c) {
        if (c) __syncthreads();

        for (int i = t; i < 64 * 32; i += 512)
            ((float4*)sW)[i] = ((const float4*)W)[c * 64 * 32 + i];

        for (int i = t; i < 128 * 16; i += 512) {
            int r = i >> 4, c4 = i & 15;
            int row = row0 + r;
            float4 v = make_float4(0.f, 0.f, 0.f, 0.f);
            if (row < n) v = ((const float4*)A)[(size_t)row * 32 + c * 16 + c4];
            ((float4*)sA)[r * 17 + c4] = v;
        }
        __syncthreads();

        const float* sArow = sA + 4 * rg * 68;
        #pragma unroll 4
        for (int k = 0; k < 64; ++k) {
            float4 w0 = sW4[k * 32 + cg     ];
            float4 w1 = sW4[k * 32 + cg + 16];
            float a0 = sArow[          k];
            float a1 = sArow[     68 + k];
            float a2 = sArow[2 *  68 + k];
            float a3 = sArow[3 *  68 + k];
            acc[0][0].x = fmaf(a0, w0.x, acc[0][0].x);
            acc[0][0].y = fmaf(a0, w0.y, acc[0][0].y);
            acc[0][0].z = fmaf(a0, w0.z, acc[0][0].z);
            acc[0][0].w = fmaf(a0, w0.w, acc[0][0].w);
            acc[0][1].x = fmaf(a0, w1.x, acc[0][1].x);
            acc[0][1].y = fmaf(a0, w1.y, acc[0][1].y);
            acc[0][1].z = fmaf(a0, w1.z, acc[0][1].z);
            acc[0][1].w = fmaf(a0, w1.w, acc[0][1].w);
            acc[1][0].x = fmaf(a1, w0.x, acc[1][0].x);
            acc[1][0].y = fmaf(a1, w0.y, acc[1][0].y);
            acc[1][0].z = fmaf(a1, w0.z, acc[1][0].z);
            acc[1][0].w = fmaf(a1, w0.w, acc[1][0].w);
            acc[1][1].x = fmaf(a1, w1.x, acc[1][1].x);
            acc[1][1].y = fmaf(a1, w1.y, acc[1][1].y);
            acc[1][1].z = fmaf(a1, w1.z, acc[1][1].z);
            acc[1][1].w = fmaf(a1, w1.w, acc[1][1].w);
            acc[2][0].x = fmaf(a2, w0.x, acc[2][0].x);
            acc[2][0].y = fmaf(a2, w0.y, acc[2][0].y);
            acc[2][0].z = fmaf(a2, w0.z, acc[2][0].z);
            acc[2][0].w = fmaf(a2, w0.w, acc[2][0].w);
            acc[2][1].x = fmaf(a2, w1.x, acc[2][1].x);
            acc[2][1].y = fmaf(a2, w1.y, acc[2][1].y);
            acc[2][1].z = fmaf(a2, w1.z, acc[2][1].z);
            acc[2][1].w = fmaf(a2, w1.w, acc[2][1].w);
            acc[3][0].x = fmaf(a3, w0.x, acc[3][0].x);
            acc[3][0].y = fmaf(a3, w0.y, acc[3][0].y);
            acc[3][0].z = fmaf(a3, w0.z, acc[3][0].z);
            acc[3][0].w = fmaf(a3, w0.w, acc[3][0].w);
            acc[3][1].x = fmaf(a3, w1.x, acc[3][1].x);
            acc[3][1].y = fmaf(a3, w1.y, acc[3][1].y);
            acc[3][1].z = fmaf(a3, w1.z, acc[3][1].z);
            acc[3][1].w = fmaf(a3, w1.w, acc[3][1].w);
        }
    }

    #pragma unroll
    for (int r = 0; r < 4; ++r) {
        int row = row0 + 4 * rg + r;
        if (row < n) {
            float s = apply_scale ? g_dego[row] : 1.0f;
            uint2* o = (uint2*)(g_tmp + (size_t)row * 128);   // 8B = 4 fp16 cols
            __half2 p0 = __floats2half2_rn(acc[r][0].x * s, acc[r][0].y * s);
            __half2 p1 = __floats2half2_rn(acc[r][0].z * s, acc[r][0].w * s);
            __half2 p2 = __floats2half2_rn(acc[r][1].x * s, acc[r][1].y * s);
            __half2 p3 = __floats2half2_rn(acc[r][1].z * s, acc[r][1].w * s);
            uint2 u0, u1;
            u0.x = *reinterpret_cast<unsigned*>(&p0);
            u0.y = *reinterpret_cast<unsigned*>(&p1);
            u1.x = *reinterpret_cast<unsigned*>(&p2);
            u1.y = *reinterpret_cast<unsigned*>(&p3);
            o[cg     ] = u0;
            o[cg + 16] = u1;
        }
    }
}

// ---------------- fp16 row loaders ----------------
__device__ __forceinline__ float4 ld_row16(const __half* base, int s, int lane) {
    uint2 v = ((const uint2*)(base + (size_t)s * 128))[lane];
    __half2 h01 = *reinterpret_cast<__half2*>(&v.x);
    __half2 h23 = *reinterpret_cast<__half2*>(&v.y);
    float2 f01 = __half22float2(h01);
    float2 f23 = __half22float2(h23);
    return make_float4(f01.x, f01.y, f23.x, f23.y);
}
__device__ __forceinline__ float4 ld_msg(int s, int lane) { return ld_row16(g_tmp, s, lane); }

// ---------------- gather-aggregate + finalize ----------------
// one warp per dst node; lane owns cols 4*lane..4*lane+3.
// Batch-8 edges: 8 independent index loads, then 8 independent message
// (+scale) loads -> MLP ~8-16 hides L2 latency.
__global__ __launch_bounds__(256) void gather_kernel(
    const float* __restrict__ b, float* __restrict__ dst_ext,
    int write_fp16, int src_scale)
{
    int v = blockIdx.x * 8 + (threadIdx.x >> 5);
    if (v >= NN) return;
    int lane = threadIdx.x & 31;

    int cnt = g_fill[v];
    if (cnt > STRIDE) cnt = STRIDE;
    const int* lst = g_ell + (size_t)v * STRIDE;

    float4 acc = make_float4(0.f, 0.f, 0.f, 0.f);
    int j = 0;
    if (src_scale) {
        for (; j + 8 <= cnt; j += 8) {
            int s0 = lst[j    ], s1 = lst[j + 1], s2 = lst[j + 2], s3 = lst[j + 3];
            int s4 = lst[j + 4], s5 = lst[j + 5], s6 = lst[j + 6], s7 = lst[j + 7];
            float c0 = g_dego[s0], c1 = g_dego[s1], c2 = g_dego[s2], c3 = g_dego[s3];
            float c4 = g_dego[s4], c5 = g_dego[s5], c6 = g_dego[s6], c7 = g_dego[s7];
            float4 a0 = ld_msg(s0, lane), a1 = ld_msg(s1, lane);
            float4 a2 = ld_msg(s2, lane), a3 = ld_msg(s3, lane);
            float4 a4 = ld_msg(s4, lane), a5 = ld_msg(s5, lane);
            float4 a6 = ld_msg(s6, lane), a7 = ld_msg(s7, lane);
            acc.x += (a0.x*c0 + a1.x*c1) + (a2.x*c2 + a3.x*c3)
                   + (a4.x*c4 + a5.x*c5) + (a6.x*c6 + a7.x*c7);
            acc.y += (a0.y*c0 + a1.y*c1) + (a2.y*c2 + a3.y*c3)
                   + (a4.y*c4 + a5.y*c5) + (a6.y*c6 + a7.y*c7);
            acc.z += (a0.z*c0 + a1.z*c1) + (a2.z*c2 + a3.z*c3)
                   + (a4.z*c4 + a5.z*c5) + (a6.z*c6 + a7.z*c7);
            acc.w += (a0.w*c0 + a1.w*c1) + (a2.w*c2 + a3.w*c3)
                   + (a4.w*c4 + a5.w*c5) + (a6.w*c6 + a7.w*c7);
        }
        for (; j + 2 <= cnt; j += 2) {
            int s0 = lst[j], s1 = lst[j + 1];
            float c0 = g_dego[s0], c1 = g_dego[s1];
            float4 a0 = ld_msg(s0, lane), a1 = ld_msg(s1, lane);
            acc.x += a0.x*c0 + a1.x*c1;
            acc.y += a0.y*c0 + a1.y*c1;
            acc.z += a0.z*c0 + a1.z*c1;
            acc.w += a0.w*c0 + a1.w*c1;
        }
        for (; j < cnt; ++j) {
            int s = lst[j];
            float c = g_dego[s];
            float4 a = ld_msg(s, lane);
            acc.x = fmaf(a.x, c, acc.x); acc.y = fmaf(a.y, c, acc.y);
            acc.z = fmaf(a.z, c, acc.z); acc.w = fmaf(a.w, c, acc.w);
        }
    } else {
        for (; j + 8 <= cnt; j += 8) {
            int s0 = lst[j    ], s1 = lst[j + 1], s2 = lst[j + 2], s3 = lst[j + 3];
            int s4 = lst[j + 4], s5 = lst[j + 5], s6 = lst[j + 6], s7 = lst[j + 7];
            float4 a0 = ld_msg(s0, lane), a1 = ld_msg(s1, lane);
            float4 a2 = ld_msg(s2, lane), a3 = ld_msg(s3, lane);
            float4 a4 = ld_msg(s4, lane), a5 = ld_msg(s5, lane);
            float4 a6 = ld_msg(s6, lane), a7 = ld_msg(s7, lane);
            acc.x += (a0.x + a1.x) + (a2.x + a3.x) + (a4.x + a5.x) + (a6.x + a7.x);
            acc.y += (a0.y + a1.y) + (a2.y + a3.y) + (a4.y + a5.y) + (a6.y + a7.y);
            acc.z += (a0.z + a1.z) + (a2.z + a3.z) + (a4.z + a5.z) + (a6.z + a7.z);
            acc.w += (a0.w + a1.w) + (a2.w + a3.w) + (a4.w + a5.w) + (a6.w + a7.w);
        }
        for (; j + 2 <= cnt; j += 2) {
            float4 a0 = ld_msg(lst[j], lane), a1 = ld_msg(lst[j + 1], lane);
            acc.x += a0.x + a1.x; acc.y += a0.y + a1.y;
            acc.z += a0.z + a1.z; acc.w += a0.w + a1.w;
        }
        for (; j < cnt; ++j) {
            float4 a = ld_msg(lst[j], lane);
            acc.x += a.x; acc.y += a.y; acc.z += a.z; acc.w += a.w;
        }
    }

    float sc = g_degi[v];
    float4 bb = ((const float4*)b)[lane];
    float4 o;
    o.x = fmaf(acc.x, sc, bb.x); o.x = o.x > 0.f ? o.x : 0.f;
    o.y = fmaf(acc.y, sc, bb.y); o.y = o.y > 0.f ? o.y : 0.f;
    o.z = fmaf(acc.z, sc, bb.z); o.z = o.z > 0.f ? o.z : 0.f;
    o.w = fmaf(acc.w, sc, bb.w); o.w = o.w > 0.f ? o.w : 0.f;

    float* dst = dst_ext ? dst_ext : g_h;
    ((float4*)(dst + (size_t)v * 128))[lane] = o;

    if (write_fp16) {               // fp16 copy of h for the classifier
        __half2 q0 = __floats2half2_rn(o.x, o.y);
        __half2 q1 = __floats2half2_rn(o.z, o.w);
        uint2 u;
        u.x = *reinterpret_cast<unsigned*>(&q0);
        u.y = *reinterpret_cast<unsigned*>(&q1);
        ((uint2*)(g_hc + (size_t)v * 128))[lane] = u;
    }
}

// ---------------- edge classifier (reads fp16 h copy) ----------------
__global__ __launch_bounds__(256) void edge_cls_kernel(
    const int* __restrict__ cs, const int* __restrict__ cd,
    const float* __restrict__ Wc, const float* __restrict__ bc,
    float* __restrict__ out)
{
    int w = threadIdx.x >> 5, lane = threadIdx.x & 31;
    int i = blockIdx.x * 8 + w;
    if (i >= ECC) return;

    int k0 = lane * 4;
    float w0s[4], w1s[4], w0d[4], w1d[4];
    #pragma unroll
    for (int j = 0; j < 4; ++j) {
        w0s[j] = __ldg(&Wc[(k0 + j) * 2    ]);
        w1s[j] = __ldg(&Wc[(k0 + j) * 2 + 1]);
        w0d[j] = __ldg(&Wc[(128 + k0 + j) * 2    ]);
        w1d[j] = __ldg(&Wc[(128 + k0 + j) * 2 + 1]);
    }

    int s = __ldg(&cs[i]);
    int d = __ldg(&cd[i]);
    float4 a = ld_row16(g_hc, s, lane);
    float4 b = ld_row16(g_hc, d, lane);

    float l0 = a.x * w0s[0] + a.y * w0s[1] + a.z * w0s[2] + a.w * w0s[3]
             + b.x * w0d[0] + b.y * w0d[1] + b.z * w0d[2] + b.w * w0d[3];
    float l1 = a.x * w1s[0] + a.y * w1s[1] + a.z * w1s[2] + a.w * w1s[3]
             + b.x * w1d[0] + b.y * w1d[1] + b.z * w1d[2] + b.w * w1d[3];

    #pragma unroll
    for (int m = 16; m > 0; m >>= 1) {
        l0 += __shfl_xor_sync(0xffffffffu, l0, m);
        l1 += __shfl_xor_sync(0xffffffffu, l1, m);
    }

    if (lane == 0) {
        float z0 = l0 + __ldg(&bc[0]);
        float z1 = l1 + __ldg(&bc[1]);
        out[(size_t)i * 2    ] = 1.0f / (1.0f + expf(-z0));
        out[(size_t)i * 2 + 1] = 1.0f / (1.0f + expf(-z1));
    }
}

// ---------------- launch ----------------
extern "C" void kernel_launch(void* const* d_in, const int* in_sizes, int n_in,
                              void* d_out, int out_size)
{
    const float* feat = (const float*)d_in[0];
    const int*   gsrc = (const int*)  d_in[1];
    const int*   gdst = (const int*)  d_in[2];
    const int*   csrc = (const int*)  d_in[3];
    const int*   cdst = (const int*)  d_in[4];
    const float* W1   = (const float*)d_in[5];
    const float* b1   = (const float*)d_in[6];
    const float* W2   = (const float*)d_in[7];
    const float* b2   = (const float*)d_in[8];
    const float* Wc   = (const float*)d_in[9];
    const float* bc   = (const float*)d_in[10];
    float* out = (float*)d_out;

    const int GEMM_SMEM = (64 * 128 + 128 * 68) * 4;  // 67,584 B -> 2 CTAs/SM
    static cudaStream_t sB;
    static cudaEvent_t evA, evB;
    static int init_done = 0;
    if (!init_done) {
        cudaFuncSetAttribute(gemm128_kernel,
                             cudaFuncAttributeMaxDynamicSharedMemorySize, GEMM_SMEM);
        cudaStreamCreateWithFlags(&sB, cudaStreamNonBlocking);
        cudaEventCreateWithFlags(&evA, cudaEventDisableTiming);
        cudaEventCreateWithFlags(&evB, cudaEventDisableTiming);
        init_done = 1;
    }

    // fork: GEMM1 independent of graph build (dego applied per-edge in gather1)
    cudaEventRecord(evA, 0);
    cudaStreamWaitEvent(sB, evA, 0);

    zero_cnt_kernel<<<(NN + 255) / 256, 256>>>();                       // launch 0
    build_graph_kernel<<<(EE + 255) / 256, 256>>>(gsrc, gdst);          // launch 1
    make_scale_kernel<<<(NN + 255) / 256, 256>>>();                     // launch 2

    gemm128_kernel<<<(NN + 127) / 128, 512, GEMM_SMEM, sB>>>(feat, 0, W1, NN, 0); // launch 3

    cudaEventRecord(evB, sB);
    cudaStreamWaitEvent(0, evB, 0);

    gather_kernel<<<(NN + 7) / 8, 256>>>(b1, nullptr, 0, 1);            // launch 4

    gemm128_kernel<<<(NN + 127) / 128, 512, GEMM_SMEM>>>(nullptr, 1, W2, NN, 1); // launch 5
    gather_kernel<<<(NN + 7) / 8, 256>>>(b2, out, 1, 0);                // launch 6

    edge_cls_kernel<<<(ECC + 7) / 8, 256>>>(csrc, cdst, Wc, bc,
                                            out + (size_t)NN * HH);     // launch 7
}